// round 10
// baseline (speedup 1.0000x reference)
#include <cuda_runtime.h>
#include <math_constants.h>

#define NPIX  256
#define NFACE 256
#define NVERT 1024

// int64 (LE) index buffers have zero odd 32-bit words (indices < 1024).
__device__ __forceinline__ bool probe_i64(const int* p) {
    bool all_zero = true;
    #pragma unroll
    for (int k = 0; k < 17; k++)
        all_zero &= (p[2 * k + 1] == 0);
    return all_zero;
}

__device__ __forceinline__ int get_idx(const void* p, int k, bool i64) {
    return i64 ? (int)((const long long*)p)[k] : ((const int*)p)[k];
}

// ---------------------------------------------------------------------------
// Fused kernel, 4 threads per pixel (face list split in quarters).
// Block = 256 threads covering a 16x4 pixel tile.
// Lane layout: lane = q*8 + sub, pixel p = warp*8 + sub  ->  all 4 quarters
// of a pixel live in ONE warp; combine via 2 shfl_xor steps.
// Grid 16x64 = 1024 blocks.
// ---------------------------------------------------------------------------
__global__ __launch_bounds__(256)
void render_kernel(const float* __restrict__ vertices,
                   const void*  __restrict__ faces,
                   const float* __restrict__ uv,
                   const void*  __restrict__ uvfaces,
                   const float* __restrict__ uvmap,
                   float*       __restrict__ out)
{
    __shared__ float4 s_f0[NFACE];   // ax, ay, bx, by
    __shared__ float4 s_f1[NFACE];   // cx, cy, Asafe, zg
    __shared__ float4 s_f2[NFACE];   // zi0, zi1, zi2, 0   (divide path only)
    __shared__ float s_u0[NFACE], s_u1[NFACE], s_u2[NFACE];
    __shared__ float s_v0[NFACE], s_v1[NFACE], s_v2[NFACE];
    __shared__ float s_min8[8];
    __shared__ int   s_probe[2];
    __shared__ int   s_cnt;
    __shared__ int   s_wcnt[8], s_woff[8];

    const float STEP = 2.0f / 255.0f;   // correctly-rounded f32 linspace step

    int tid  = threadIdx.y * 16 + threadIdx.x;
    int warp = tid >> 5, lane = tid & 31;
    int j0 = blockIdx.x * 16;           // 16 columns
    int i0 = blockIdx.y * 4;            // 4 rows

    // ---- probes: one thread per block ----
    if (tid == 0) {
        s_probe[0] = probe_i64((const int*)faces) ? 1 : 0;
        s_probe[1] = probe_i64((const int*)uvfaces) ? 1 : 0;
    }

    // ---- zinit = min over vertices[:,2], warp-shuffle reduction ----
    float zm = CUDART_INF_F;
    #pragma unroll
    for (int q = 0; q < 4; q++)
        zm = fminf(zm, vertices[(tid + q * 256) * 3 + 2]);
    #pragma unroll
    for (int o = 16; o > 0; o >>= 1)
        zm = fminf(zm, __shfl_xor_sync(0xffffffffu, zm, o));
    if (lane == 0) s_min8[warp] = zm;
    __syncthreads();                               // barrier 1

    bool f_i64  = (s_probe[0] != 0);
    bool uf_i64 = (s_probe[1] != 0);
    float zinit = s_min8[0];
    #pragma unroll
    for (int w = 1; w < 8; w++) zinit = fminf(zinit, s_min8[w]);

    // ---- per-face precompute (thread owns face `tid`) ----
    int i0v = get_idx(faces, tid * 3 + 0, f_i64);
    int i1v = get_idx(faces, tid * 3 + 1, f_i64);
    int i2v = get_idx(faces, tid * 3 + 2, f_i64);
    i0v = min(max(i0v, 0), NVERT - 1);
    i1v = min(max(i1v, 0), NVERT - 1);
    i2v = min(max(i2v, 0), NVERT - 1);

    float ax = vertices[i0v * 3 + 0], ay = vertices[i0v * 3 + 1], az = vertices[i0v * 3 + 2];
    float bx = vertices[i1v * 3 + 0], by = vertices[i1v * 3 + 1], bz = vertices[i1v * 3 + 2];
    float cx = vertices[i2v * 3 + 0], cy = vertices[i2v * 3 + 1], cz = vertices[i2v * 3 + 2];

    // area2d (XLA-contracted): A = fma(bx-ax, cy-ay, -((by-ay)*(cx-ax)))
    float t2nd = __fmul_rn(__fsub_rn(by, ay), __fsub_rn(cx, ax));
    float A    = __fmaf_rn(__fsub_rn(bx, ax), __fsub_rn(cy, ay), -t2nd);
    bool  valid = (A >= 1e-9f);

    // tile NDC bounds (rows i0..i0+3), padded for edge-fn fp error band
    float pad = 0.02f;
    float tile_xmin = __fadd_rn(__fmul_rn((float)j0,        STEP), -1.0f) - pad;
    float tile_xmax = __fadd_rn(__fmul_rn((float)(j0 + 15), STEP), -1.0f) + pad;
    float tile_ymin = __fadd_rn(__fmul_rn((float)(255 - (i0 + 3)), STEP), -1.0f) - pad;
    float tile_ymax = __fadd_rn(__fmul_rn((float)(255 - i0),       STEP), -1.0f) + pad;

    float bxmin = fminf(ax, fminf(bx, cx)), bxmax = fmaxf(ax, fmaxf(bx, cx));
    float bymin = fminf(ay, fminf(by, cy)), bymax = fmaxf(ay, fmaxf(by, cy));

    bool ok = valid &&
              (bxmax > tile_xmin) && (bxmin < tile_xmax) &&
              (bymax > tile_ymin) && (bymin < tile_ymax);

    // ---- ordered compaction (preserves face order -> argmax tie rule) ----
    unsigned m = __ballot_sync(0xffffffffu, ok);
    if (lane == 0) s_wcnt[warp] = __popc(m);
    __syncthreads();                               // barrier 2
    if (tid == 0) {
        int s = 0;
        #pragma unroll
        for (int w = 0; w < 8; w++) { s_woff[w] = s; s += s_wcnt[w]; }
        s_cnt = s;
    }
    __syncthreads();                               // barrier 3

    if (ok) {
        // expensive per-face work only for surviving faces (~30%)
        float Asafe = (fabsf(A) < 1e-9f) ? 1.0f : A;
        float zi0 = __fdiv_rn(1.0f, az);
        float zi1 = __fdiv_rn(1.0f, bz);
        float zi2 = __fdiv_rn(1.0f, cz);
        // interpolated Z <= max vertex z; 1.0001 margin covers ~2e-6 rounding
        float zg = __fmul_rn(fmaxf(az, fmaxf(bz, cz)), 1.0001f);

        int t0 = get_idx(uvfaces, tid * 3 + 0, uf_i64);
        int t1 = get_idx(uvfaces, tid * 3 + 1, uf_i64);
        int t2 = get_idx(uvfaces, tid * 3 + 2, uf_i64);
        t0 = min(max(t0, 0), 1023);
        t1 = min(max(t1, 0), 1023);
        t2 = min(max(t2, 0), 1023);

        float un0 = __fmaf_rn(uv[t0 * 2 + 0], 2.0f, -1.0f);
        float vn0 = __fmaf_rn(uv[t0 * 2 + 1], 2.0f, -1.0f);
        float un1 = __fmaf_rn(uv[t1 * 2 + 0], 2.0f, -1.0f);
        float vn1 = __fmaf_rn(uv[t1 * 2 + 1], 2.0f, -1.0f);
        float un2 = __fmaf_rn(uv[t2 * 2 + 0], 2.0f, -1.0f);
        float vn2 = __fmaf_rn(uv[t2 * 2 + 1], 2.0f, -1.0f);

        int p = s_woff[warp] + __popc(m & ((1u << lane) - 1u));
        s_f0[p] = make_float4(ax, ay, bx, by);
        s_f1[p] = make_float4(cx, cy, Asafe, zg);
        s_f2[p] = make_float4(zi0, zi1, zi2, 0.0f);
        s_u0[p] = __fmul_rn(un0, zi0); s_v0[p] = __fmul_rn(vn0, zi0);
        s_u1[p] = __fmul_rn(un1, zi1); s_v1[p] = __fmul_rn(vn1, zi1);
        s_u2[p] = __fmul_rn(un2, zi2); s_v2[p] = __fmul_rn(vn2, zi2);
    }
    __syncthreads();                               // barrier 4
    int cnt = s_cnt;

    // ---- raster: 4 threads per pixel. lane = q*8+sub, pixel = warp*8+sub ----
    int q   = lane >> 3;
    int sub = lane & 7;
    int p   = warp * 8 + sub;           // 0..63 within the 16x4 tile
    int j   = j0 + (p & 15);
    int i   = i0 + (p >> 4);
    // pts grid is constant-folded by XLA (round-per-op): plain mul+add, NOT fma
    float px = __fadd_rn(__fmul_rn((float)j,         STEP), -1.0f);
    float py = __fadd_rn(__fmul_rn((float)(255 - i), STEP), -1.0f);

    int kbeg = (q * cnt) >> 2;
    int kend = ((q + 1) * cnt) >> 2;

    float best = -CUDART_INF_F;
    int   win = -1;
    float w1w = 0.f, w2w = 0.f, w3w = 0.f;

    for (int k = kbeg; k < kend; k++) {
        float4 f0 = s_f0[k];            // ax ay bx by
        float4 f1 = s_f1[k];            // cx cy As zg
        // XLA-contracted edge: fma(px-a.x, c.y-a.y, -((py-a.y)*(c.x-a.x)))
        float tAB = __fmul_rn(__fsub_rn(py, f0.w), __fsub_rn(f0.x, f0.z));
        float pAB = __fmaf_rn(__fsub_rn(px, f0.z), __fsub_rn(f0.y, f0.w), -tAB);
        float tCB = __fmul_rn(__fsub_rn(py, f1.y), __fsub_rn(f0.z, f1.x));
        float pCB = __fmaf_rn(__fsub_rn(px, f1.x), __fsub_rn(f0.w, f1.y), -tCB);
        float tCA = __fmul_rn(__fsub_rn(py, f0.y), __fsub_rn(f1.x, f0.x));
        float pCA = __fmaf_rn(__fsub_rn(px, f0.x), __fsub_rn(f1.y, f0.y), -tCA);
        if (pAB > 0.0f && pCB > 0.0f && pCA > 0.0f && f1.w > best) {
            float4 f2 = s_f2[k];        // zi0 zi1 zi2
            float w1 = __fdiv_rn(pCB, f1.z);
            float w2 = __fdiv_rn(pCA, f1.z);
            float w3 = __fsub_rn(__fsub_rn(1.0f, w1), w2);
            float zp = __fmaf_rn(w3, f2.z,
                       __fmaf_rn(w1, f2.x, __fmul_rn(w2, f2.y)));
            float Z = __fdiv_rn(1.0f, zp);
            if (Z >= zinit && Z > best) {   // strict > keeps first-index ties
                best = Z; win = k;
                w1w = w1; w2w = w2; w3w = w3;
            }
        }
    }

    // ---- combine quarters: winner = max Z, tie -> lower face index.
    //      Quarter ranges are disjoint & ordered, so this IS global argmax. ----
    #pragma unroll
    for (int off = 8; off <= 16; off <<= 1) {
        float obest = __shfl_xor_sync(0xffffffffu, best, off);
        int   owin  = __shfl_xor_sync(0xffffffffu, win, off);
        float ow1   = __shfl_xor_sync(0xffffffffu, w1w, off);
        float ow2   = __shfl_xor_sync(0xffffffffu, w2w, off);
        float ow3   = __shfl_xor_sync(0xffffffffu, w3w, off);
        bool take = (obest > best) || (obest == best && owin >= 0 && owin < win);
        if (take) {
            best = obest; win = owin; w1w = ow1; w2w = ow2; w3w = ow3;
        }
    }

    if (q == 0) {
        // ---- shade winner (quarter-0 thread only) ----
        float r = 0.0f, g = 0.0f, b = 0.0f, h = 0.0f;
        if (win >= 0) {
            float uP = __fmaf_rn(w3w, s_u2[win],
                       __fmaf_rn(w1w, s_u0[win], __fmul_rn(w2w, s_u1[win])));
            float vP = __fmaf_rn(w3w, s_v2[win],
                       __fmaf_rn(w1w, s_v0[win], __fmul_rn(w2w, s_v1[win])));
            float Zw = best;                 // bitwise == reference Zw
            float gx = __fmul_rn(uP, Zw);
            float gy = __fmul_rn(vP, Zw);

            float x = __fmul_rn(__fmaf_rn(__fadd_rn(gx, 1.0f), 256.0f, -1.0f), 0.5f);
            float y = __fmul_rn(__fmaf_rn(__fadd_rn(gy, 1.0f), 256.0f, -1.0f), 0.5f);
            float x0 = floorf(x), y0 = floorf(y);
            float x1 = __fadd_rn(x0, 1.0f), y1 = __fadd_rn(y0, 1.0f);
            float wx1 = __fsub_rn(x, x0), wx0 = __fsub_rn(1.0f, wx1);
            float wy1 = __fsub_rn(y, y0), wy0 = __fsub_rn(1.0f, wy1);

            float f00 = (x0 >= 0.0f && x0 <= 255.0f && y0 >= 0.0f && y0 <= 255.0f) ? 1.0f : 0.0f;
            float f10 = (x1 >= 0.0f && x1 <= 255.0f && y0 >= 0.0f && y0 <= 255.0f) ? 1.0f : 0.0f;
            float f01 = (x0 >= 0.0f && x0 <= 255.0f && y1 >= 0.0f && y1 <= 255.0f) ? 1.0f : 0.0f;
            float f11 = (x1 >= 0.0f && x1 <= 255.0f && y1 >= 0.0f && y1 <= 255.0f) ? 1.0f : 0.0f;

            int ix0 = (int)fminf(fmaxf(x0, 0.0f), 255.0f);
            int iy0 = (int)fminf(fmaxf(y0, 0.0f), 255.0f);
            int ix1 = (int)fminf(fmaxf(x1, 0.0f), 255.0f);
            int iy1 = (int)fminf(fmaxf(y1, 0.0f), 255.0f);

            float c00 = __fmul_rn(wx0, wy0);
            float c10 = __fmul_rn(wx1, wy0);
            float c01 = __fmul_rn(wx0, wy1);
            float c11 = __fmul_rn(wx1, wy1);

            int o00 = iy0 * 256 + ix0;
            int o10 = iy0 * 256 + ix1;
            int o01 = iy1 * 256 + ix0;
            int o11 = iy1 * 256 + ix1;

            float rgb[3];
            #pragma unroll
            for (int c = 0; c < 3; c++) {
                const float* im = uvmap + c * 65536;
                float g00 = __fmul_rn(__ldg(im + o00), f00);
                float g10 = __fmul_rn(__ldg(im + o10), f10);
                float g01 = __fmul_rn(__ldg(im + o01), f01);
                float g11 = __fmul_rn(__ldg(im + o11), f11);
                float acc = __fmaf_rn(g00, c00, __fmul_rn(g10, c10));
                acc = __fmaf_rn(g01, c01, acc);
                acc = __fmaf_rn(g11, c11, acc);
                rgb[c] = acc;
            }
            r = rgb[0]; g = rgb[1]; b = rgb[2]; h = 1.0f;
        }

        int pix = i * 256 + j;
        out[0 * 65536 + pix] = r;
        out[1 * 65536 + pix] = g;
        out[2 * 65536 + pix] = b;
        out[3 * 65536 + pix] = h;
    }
}

// ---------------------------------------------------------------------------
extern "C" void kernel_launch(void* const* d_in, const int* in_sizes, int n_in,
                              void* d_out, int out_size)
{
    const float* vertices = (const float*)d_in[0];      // (1024,3) f32
    const void*  faces    = (const void*)d_in[1];       // (256,3)  int32/int64
    const float* uv       = (const float*)d_in[2];      // (1024,2) f32
    const void*  uvfaces  = (const void*)d_in[3];       // (256,3)  int32/int64
    const float* uvmap    = (const float*)d_in[4];      // (3,256,256) f32
    float*       out      = (float*)d_out;              // (4,256,256) f32

    render_kernel<<<dim3(16, 64), dim3(16, 16)>>>(vertices, faces, uv, uvfaces,
                                                  uvmap, out);
}

// round 11
// speedup vs baseline: 1.0523x; 1.0523x over previous
#include <cuda_runtime.h>
#include <math_constants.h>

#define NPIX  256
#define NFACE 256
#define NVERT 1024

// int64 (LE) index buffers have zero odd 32-bit words (indices < 1024).
__device__ __forceinline__ bool probe_i64(const int* p) {
    bool all_zero = true;
    #pragma unroll
    for (int k = 0; k < 9; k++)
        all_zero &= (p[2 * k + 1] == 0);
    return all_zero;
}

__device__ __forceinline__ int get_idx(const void* p, int k, bool i64) {
    return i64 ? (int)((const long long*)p)[k] : ((const int*)p)[k];
}

// ---------------------------------------------------------------------------
// Fused kernel, 4 threads per pixel (face list split in quarters).
// Block = 512 threads covering a 16x8 pixel tile (prologue runs in warps 0-7
// only; warps 8-15 idle at the barrier -> half the prologue issues of R10).
// Lane layout: lane = q*8 + sub, pixel p = warp*8 + sub -> all 4 quarters of
// a pixel live in ONE warp; combine via 2 shfl_xor steps.
// Grid 16x32 = 512 blocks.
// ---------------------------------------------------------------------------
__global__ __launch_bounds__(512)
void render_kernel(const float* __restrict__ vertices,
                   const void*  __restrict__ faces,
                   const float* __restrict__ uv,
                   const void*  __restrict__ uvfaces,
                   const float* __restrict__ uvmap,
                   float*       __restrict__ out)
{
    __shared__ float4 s_f0[NFACE];   // ax, ay, bx, by
    __shared__ float4 s_f1[NFACE];   // cx, cy, Asafe, zg
    __shared__ float4 s_f2[NFACE];   // zi0, zi1, zi2, 0   (divide path only)
    __shared__ float s_u0[NFACE], s_u1[NFACE], s_u2[NFACE];
    __shared__ float s_v0[NFACE], s_v1[NFACE], s_v2[NFACE];
    __shared__ float s_min16[16];
    __shared__ int   s_probe[2];
    __shared__ int   s_cnt;
    __shared__ int   s_wcnt[8], s_woff[8];

    const float STEP = 2.0f / 255.0f;   // correctly-rounded f32 linspace step

    int tid  = threadIdx.y * 16 + threadIdx.x;      // 0..511
    int warp = tid >> 5, lane = tid & 31;
    int j0 = blockIdx.x * 16;           // 16 columns
    int i0 = blockIdx.y * 8;            // 8 rows

    // ---- probes: one thread per block ----
    if (tid == 0) {
        s_probe[0] = probe_i64((const int*)faces) ? 1 : 0;
        s_probe[1] = probe_i64((const int*)uvfaces) ? 1 : 0;
    }

    // ---- zinit = min over vertices[:,2]: 2 loads/thread + warp reduction ----
    float zm = fminf(vertices[tid * 3 + 2], vertices[(tid + 512) * 3 + 2]);
    #pragma unroll
    for (int o = 16; o > 0; o >>= 1)
        zm = fminf(zm, __shfl_xor_sync(0xffffffffu, zm, o));
    if (lane == 0) s_min16[warp] = zm;

    // ---- per-face precompute: warps 0-7 only (thread owns face `tid`) ----
    bool lead = (tid < NFACE);
    unsigned m = 0;
    bool ok = false;
    float ax, ay, az, bx, by, bz, cx, cy, cz, A;

    if (lead) {
        // probe result needed; read after barrier below -- so stage loads that
        // don't depend on it? get_idx needs it. Defer face fetch past barrier.
    }
    __syncthreads();                               // barrier 1

    bool f_i64  = (s_probe[0] != 0);
    bool uf_i64 = (s_probe[1] != 0);
    float zinit = s_min16[0];
    #pragma unroll
    for (int w = 1; w < 16; w++) zinit = fminf(zinit, s_min16[w]);

    if (lead) {
        int i0v = get_idx(faces, tid * 3 + 0, f_i64);
        int i1v = get_idx(faces, tid * 3 + 1, f_i64);
        int i2v = get_idx(faces, tid * 3 + 2, f_i64);
        i0v = min(max(i0v, 0), NVERT - 1);
        i1v = min(max(i1v, 0), NVERT - 1);
        i2v = min(max(i2v, 0), NVERT - 1);

        ax = vertices[i0v * 3 + 0]; ay = vertices[i0v * 3 + 1]; az = vertices[i0v * 3 + 2];
        bx = vertices[i1v * 3 + 0]; by = vertices[i1v * 3 + 1]; bz = vertices[i1v * 3 + 2];
        cx = vertices[i2v * 3 + 0]; cy = vertices[i2v * 3 + 1]; cz = vertices[i2v * 3 + 2];

        // area2d (XLA-contracted): A = fma(bx-ax, cy-ay, -((by-ay)*(cx-ax)))
        float t2nd = __fmul_rn(__fsub_rn(by, ay), __fsub_rn(cx, ax));
        A = __fmaf_rn(__fsub_rn(bx, ax), __fsub_rn(cy, ay), -t2nd);
        bool valid = (A >= 1e-9f);

        // tile NDC bounds (rows i0..i0+7), padded for edge-fn fp error band
        float pad = 0.02f;
        float tile_xmin = __fadd_rn(__fmul_rn((float)j0,        STEP), -1.0f) - pad;
        float tile_xmax = __fadd_rn(__fmul_rn((float)(j0 + 15), STEP), -1.0f) + pad;
        float tile_ymin = __fadd_rn(__fmul_rn((float)(255 - (i0 + 7)), STEP), -1.0f) - pad;
        float tile_ymax = __fadd_rn(__fmul_rn((float)(255 - i0),       STEP), -1.0f) + pad;

        float bxmin = fminf(ax, fminf(bx, cx)), bxmax = fmaxf(ax, fmaxf(bx, cx));
        float bymin = fminf(ay, fminf(by, cy)), bymax = fmaxf(ay, fmaxf(by, cy));

        ok = valid &&
             (bxmax > tile_xmin) && (bxmin < tile_xmax) &&
             (bymax > tile_ymin) && (bymin < tile_ymax);

        // ---- ordered compaction (preserves face order -> argmax ties) ----
        m = __ballot_sync(0xffffffffu, ok);
        if (lane == 0) s_wcnt[warp] = __popc(m);
    }
    __syncthreads();                               // barrier 2
    if (tid == 0) {
        int s = 0;
        #pragma unroll
        for (int w = 0; w < 8; w++) { s_woff[w] = s; s += s_wcnt[w]; }
        s_cnt = s;
    }
    __syncthreads();                               // barrier 3

    if (ok) {
        // expensive per-face work only for surviving faces
        float Asafe = (fabsf(A) < 1e-9f) ? 1.0f : A;
        float zi0 = __fdiv_rn(1.0f, az);
        float zi1 = __fdiv_rn(1.0f, bz);
        float zi2 = __fdiv_rn(1.0f, cz);
        // interpolated Z <= max vertex z; 1.0001 margin covers ~2e-6 rounding
        float zg = __fmul_rn(fmaxf(az, fmaxf(bz, cz)), 1.0001f);

        int t0 = get_idx(uvfaces, tid * 3 + 0, uf_i64);
        int t1 = get_idx(uvfaces, tid * 3 + 1, uf_i64);
        int t2 = get_idx(uvfaces, tid * 3 + 2, uf_i64);
        t0 = min(max(t0, 0), 1023);
        t1 = min(max(t1, 0), 1023);
        t2 = min(max(t2, 0), 1023);

        float un0 = __fmaf_rn(uv[t0 * 2 + 0], 2.0f, -1.0f);
        float vn0 = __fmaf_rn(uv[t0 * 2 + 1], 2.0f, -1.0f);
        float un1 = __fmaf_rn(uv[t1 * 2 + 0], 2.0f, -1.0f);
        float vn1 = __fmaf_rn(uv[t1 * 2 + 1], 2.0f, -1.0f);
        float un2 = __fmaf_rn(uv[t2 * 2 + 0], 2.0f, -1.0f);
        float vn2 = __fmaf_rn(uv[t2 * 2 + 1], 2.0f, -1.0f);

        int p = s_woff[warp] + __popc(m & ((1u << lane) - 1u));
        s_f0[p] = make_float4(ax, ay, bx, by);
        s_f1[p] = make_float4(cx, cy, Asafe, zg);
        s_f2[p] = make_float4(zi0, zi1, zi2, 0.0f);
        s_u0[p] = __fmul_rn(un0, zi0); s_v0[p] = __fmul_rn(vn0, zi0);
        s_u1[p] = __fmul_rn(un1, zi1); s_v1[p] = __fmul_rn(vn1, zi1);
        s_u2[p] = __fmul_rn(un2, zi2); s_v2[p] = __fmul_rn(vn2, zi2);
    }
    __syncthreads();                               // barrier 4
    int cnt = s_cnt;

    // ---- raster: 4 threads/pixel. lane = q*8+sub, pixel = warp*8+sub ----
    int q   = lane >> 3;
    int sub = lane & 7;
    int p   = warp * 8 + sub;           // 0..127 within the 16x8 tile
    int j   = j0 + (p & 15);
    int i   = i0 + (p >> 4);
    // pts grid is constant-folded by XLA (round-per-op): plain mul+add, NOT fma
    float px = __fadd_rn(__fmul_rn((float)j,         STEP), -1.0f);
    float py = __fadd_rn(__fmul_rn((float)(255 - i), STEP), -1.0f);

    int kbeg = (q * cnt) >> 2;
    int kend = ((q + 1) * cnt) >> 2;

    float best = -CUDART_INF_F;
    int   win = -1;
    float w1w = 0.f, w2w = 0.f, w3w = 0.f;

    #pragma unroll 2
    for (int k = kbeg; k < kend; k++) {
        float4 f0 = s_f0[k];            // ax ay bx by
        float4 f1 = s_f1[k];            // cx cy As zg
        // XLA-contracted edge: fma(px-a.x, c.y-a.y, -((py-a.y)*(c.x-a.x)))
        float tAB = __fmul_rn(__fsub_rn(py, f0.w), __fsub_rn(f0.x, f0.z));
        float pAB = __fmaf_rn(__fsub_rn(px, f0.z), __fsub_rn(f0.y, f0.w), -tAB);
        float tCB = __fmul_rn(__fsub_rn(py, f1.y), __fsub_rn(f0.z, f1.x));
        float pCB = __fmaf_rn(__fsub_rn(px, f1.x), __fsub_rn(f0.w, f1.y), -tCB);
        float tCA = __fmul_rn(__fsub_rn(py, f0.y), __fsub_rn(f1.x, f0.x));
        float pCA = __fmaf_rn(__fsub_rn(px, f0.x), __fsub_rn(f1.y, f0.y), -tCA);
        if (pAB > 0.0f && pCB > 0.0f && pCA > 0.0f && f1.w > best) {
            float4 f2 = s_f2[k];        // zi0 zi1 zi2
            float w1 = __fdiv_rn(pCB, f1.z);
            float w2 = __fdiv_rn(pCA, f1.z);
            float w3 = __fsub_rn(__fsub_rn(1.0f, w1), w2);
            float zp = __fmaf_rn(w3, f2.z,
                       __fmaf_rn(w1, f2.x, __fmul_rn(w2, f2.y)));
            float Z = __fdiv_rn(1.0f, zp);
            if (Z >= zinit && Z > best) {   // strict > keeps first-index ties
                best = Z; win = k;
                w1w = w1; w2w = w2; w3w = w3;
            }
        }
    }

    // ---- combine quarters: max Z, tie -> lower face index.
    //      Quarter ranges are disjoint & ordered, so this IS global argmax. ----
    #pragma unroll
    for (int off = 8; off <= 16; off <<= 1) {
        float obest = __shfl_xor_sync(0xffffffffu, best, off);
        int   owin  = __shfl_xor_sync(0xffffffffu, win, off);
        float ow1   = __shfl_xor_sync(0xffffffffu, w1w, off);
        float ow2   = __shfl_xor_sync(0xffffffffu, w2w, off);
        float ow3   = __shfl_xor_sync(0xffffffffu, w3w, off);
        bool take = (obest > best) || (obest == best && owin >= 0 && owin < win);
        if (take) {
            best = obest; win = owin; w1w = ow1; w2w = ow2; w3w = ow3;
        }
    }

    if (q == 0) {
        // ---- shade winner (quarter-0 thread only) ----
        float r = 0.0f, g = 0.0f, b = 0.0f, h = 0.0f;
        if (win >= 0) {
            float uP = __fmaf_rn(w3w, s_u2[win],
                       __fmaf_rn(w1w, s_u0[win], __fmul_rn(w2w, s_u1[win])));
            float vP = __fmaf_rn(w3w, s_v2[win],
                       __fmaf_rn(w1w, s_v0[win], __fmul_rn(w2w, s_v1[win])));
            float Zw = best;                 // bitwise == reference Zw
            float gx = __fmul_rn(uP, Zw);
            float gy = __fmul_rn(vP, Zw);

            float x = __fmul_rn(__fmaf_rn(__fadd_rn(gx, 1.0f), 256.0f, -1.0f), 0.5f);
            float y = __fmul_rn(__fmaf_rn(__fadd_rn(gy, 1.0f), 256.0f, -1.0f), 0.5f);
            float x0 = floorf(x), y0 = floorf(y);
            float x1 = __fadd_rn(x0, 1.0f), y1 = __fadd_rn(y0, 1.0f);
            float wx1 = __fsub_rn(x, x0), wx0 = __fsub_rn(1.0f, wx1);
            float wy1 = __fsub_rn(y, y0), wy0 = __fsub_rn(1.0f, wy1);

            float f00 = (x0 >= 0.0f && x0 <= 255.0f && y0 >= 0.0f && y0 <= 255.0f) ? 1.0f : 0.0f;
            float f10 = (x1 >= 0.0f && x1 <= 255.0f && y0 >= 0.0f && y0 <= 255.0f) ? 1.0f : 0.0f;
            float f01 = (x0 >= 0.0f && x0 <= 255.0f && y1 >= 0.0f && y1 <= 255.0f) ? 1.0f : 0.0f;
            float f11 = (x1 >= 0.0f && x1 <= 255.0f && y1 >= 0.0f && y1 <= 255.0f) ? 1.0f : 0.0f;

            int ix0 = (int)fminf(fmaxf(x0, 0.0f), 255.0f);
            int iy0 = (int)fminf(fmaxf(y0, 0.0f), 255.0f);
            int ix1 = (int)fminf(fmaxf(x1, 0.0f), 255.0f);
            int iy1 = (int)fminf(fmaxf(y1, 0.0f), 255.0f);

            float c00 = __fmul_rn(wx0, wy0);
            float c10 = __fmul_rn(wx1, wy0);
            float c01 = __fmul_rn(wx0, wy1);
            float c11 = __fmul_rn(wx1, wy1);

            int o00 = iy0 * 256 + ix0;
            int o10 = iy0 * 256 + ix1;
            int o01 = iy1 * 256 + ix0;
            int o11 = iy1 * 256 + ix1;

            float rgb[3];
            #pragma unroll
            for (int c = 0; c < 3; c++) {
                const float* im = uvmap + c * 65536;
                float g00 = __fmul_rn(__ldg(im + o00), f00);
                float g10 = __fmul_rn(__ldg(im + o10), f10);
                float g01 = __fmul_rn(__ldg(im + o01), f01);
                float g11 = __fmul_rn(__ldg(im + o11), f11);
                float acc = __fmaf_rn(g00, c00, __fmul_rn(g10, c10));
                acc = __fmaf_rn(g01, c01, acc);
                acc = __fmaf_rn(g11, c11, acc);
                rgb[c] = acc;
            }
            r = rgb[0]; g = rgb[1]; b = rgb[2]; h = 1.0f;
        }

        int pix = i * 256 + j;
        out[0 * 65536 + pix] = r;
        out[1 * 65536 + pix] = g;
        out[2 * 65536 + pix] = b;
        out[3 * 65536 + pix] = h;
    }
}

// ---------------------------------------------------------------------------
extern "C" void kernel_launch(void* const* d_in, const int* in_sizes, int n_in,
                              void* d_out, int out_size)
{
    const float* vertices = (const float*)d_in[0];      // (1024,3) f32
    const void*  faces    = (const void*)d_in[1];       // (256,3)  int32/int64
    const float* uv       = (const float*)d_in[2];      // (1024,2) f32
    const void*  uvfaces  = (const void*)d_in[3];       // (256,3)  int32/int64
    const float* uvmap    = (const float*)d_in[4];      // (3,256,256) f32
    float*       out      = (float*)d_out;              // (4,256,256) f32

    render_kernel<<<dim3(16, 32), dim3(16, 32)>>>(vertices, faces, uv, uvfaces,
                                                  uvmap, out);
}